// round 3
// baseline (speedup 1.0000x reference)
#include <cuda_runtime.h>
#include <cstdint>

// ---------------------------------------------------------------------------
// SAM spatial self-attention, algebraically reduced:
//   softmax scores: s_nm = r_n . x_m  with r_n = (Wq^T Wk)^T x_n + Wk^T bq
//   output:         y    = (Wo Wv) (attn . X)_n + (Wo bv + bo) + x_n
// All fp32; packed fma.rn.f32x2 for 2x FMA issue rate on sm_103a.
// ---------------------------------------------------------------------------

namespace {
constexpr int BATCH = 8;
constexpr int CIN   = 32;
constexpr int COUT  = 64;
constexpr int NPIX  = 4096;   // 64*64
constexpr int TQ    = 128;    // queries per block (1 per thread)
constexpr int TK    = 128;    // keys per smem tile
constexpr int NT    = NPIX / TK;
constexpr float LOG2E = 1.4426950408889634f;
constexpr float SHIFT = 14.0f;  // uniform log2-shift; cancels in softmax
}

// scratch (allocation-free rule: __device__ globals)
__device__ __align__(16) float g_Xt[BATCH * NPIX * CIN];   // x transposed: [b][n][c]
__device__ __align__(16) float g_Qt[BATCH * NPIX * CIN];   // r-vectors (log2-scaled)
__device__ __align__(16) float g_At[CIN * CIN];            // log2e * (Wq^T Wk)^T
__device__ __align__(16) float g_cv[CIN];                  // log2e * Wk^T bq
__device__ __align__(16) float g_WovP[CIN * CIN];          // (Wo Wv)^T  [j][o]
__device__ __align__(16) float g_b2[CIN];                  // Wo bv + bo

using ull = unsigned long long;

__device__ __forceinline__ void ffma2(ull& d, ull a, ull b) {
    asm("fma.rn.f32x2 %0, %1, %2, %0;" : "+l"(d) : "l"(a), "l"(b));
}
__device__ __forceinline__ void fadd2(ull& d, ull b) {
    asm("add.rn.f32x2 %0, %0, %1;" : "+l"(d) : "l"(b));
}
__device__ __forceinline__ void fmul2(ull& d, ull b) {
    asm("mul.rn.f32x2 %0, %0, %1;" : "+l"(d) : "l"(b));
}
__device__ __forceinline__ ull pack1(float p) {
    ull r; asm("mov.b64 %0, {%1, %1};" : "=l"(r) : "f"(p)); return r;
}
__device__ __forceinline__ float2 unpack2(ull v) {
    float2 r; asm("mov.b64 {%0, %1}, %2;" : "=f"(r.x), "=f"(r.y) : "l"(v)); return r;
}
__device__ __forceinline__ void cp_async16(void* s, const void* g) {
    unsigned sa = (unsigned)__cvta_generic_to_shared(s);
    asm volatile("cp.async.cg.shared.global [%0], [%1], 16;" :: "r"(sa), "l"(g));
}
__device__ __forceinline__ void cp_commit() { asm volatile("cp.async.commit_group;"); }
template<int N> __device__ __forceinline__ void cp_wait() {
    asm volatile("cp.async.wait_group %0;" :: "n"(N));
}

// ---------------------------------------------------------------------------
// Derived weights (tiny; 1 block)
// ---------------------------------------------------------------------------
__global__ void derive_kernel(const float* __restrict__ wq, const float* __restrict__ bq,
                              const float* __restrict__ wk, const float* __restrict__ wv,
                              const float* __restrict__ wo, const float* __restrict__ bv,
                              const float* __restrict__ bo) {
    int t = threadIdx.x;          // 1024 threads
    int i = t >> 5, j = t & 31;
    // At[i][j] = sum_o wk[o][i] * wq[o][j]   (so r[i] = sum_j At[i][j] x[j])
    float a = 0.f;
    for (int o = 0; o < COUT; ++o) a += wk[o * CIN + i] * wq[o * CIN + j];
    g_At[i * CIN + j] = a * LOG2E;
    // WovP[i][j] = (Wo Wv)[j][i]  (row i = channel j of out-vec, col j = output o)
    float w = 0.f;
    for (int cc = 0; cc < COUT; ++cc) w += wo[j * COUT + cc] * wv[cc * CIN + i];
    g_WovP[i * CIN + j] = w;
    if (t < CIN) {
        float c = 0.f;
        for (int o = 0; o < COUT; ++o) c += bq[o] * wk[o * CIN + t];
        g_cv[t] = c * LOG2E;
        float b = bo[t];
        for (int cc = 0; cc < COUT; ++cc) b += wo[t * COUT + cc] * bv[cc];
        g_b2[t] = b;
    }
}

// ---------------------------------------------------------------------------
// Transpose x (B, C, N) -> Xt (B, N, C)
// ---------------------------------------------------------------------------
__global__ void transpose_kernel(const float* __restrict__ x) {
    __shared__ float s[32][33];
    int b  = blockIdx.y;
    int n0 = blockIdx.x * 32;
    int tx = threadIdx.x, ty = threadIdx.y;
    s[ty][tx] = x[((size_t)b * CIN + ty) * NPIX + n0 + tx];
    __syncthreads();
    g_Xt[((size_t)b * NPIX + n0 + ty) * CIN + tx] = s[tx][ty];
}

// ---------------------------------------------------------------------------
// r-projection: Qt[n] = At * Xt[n] + c   (already log2e-scaled)
// ---------------------------------------------------------------------------
__global__ void qproj_kernel() {
    __shared__ float sA[CIN * CIN];
    __shared__ float sc[CIN];
    int t = threadIdx.x;                        // 128 threads
    for (int k = t; k < CIN * CIN; k += TQ) sA[k] = g_At[k];
    if (t < CIN) sc[t] = g_cv[t];
    __syncthreads();
    int gp = blockIdx.x * TQ + t;               // global pixel 0..32767
    float xr[CIN];
    const float4* xp = reinterpret_cast<const float4*>(g_Xt + (size_t)gp * CIN);
#pragma unroll
    for (int k = 0; k < 8; ++k) {
        float4 v = xp[k];
        xr[4*k] = v.x; xr[4*k+1] = v.y; xr[4*k+2] = v.z; xr[4*k+3] = v.w;
    }
    float4* qo = reinterpret_cast<float4*>(g_Qt + (size_t)gp * CIN);
#pragma unroll
    for (int i = 0; i < CIN; i += 4) {
        float r[4];
#pragma unroll
        for (int u = 0; u < 4; ++u) {
            float acc = sc[i + u];
#pragma unroll
            for (int jj = 0; jj < CIN; ++jj) acc += sA[(i + u) * CIN + jj] * xr[jj];
            r[u] = acc;
        }
        qo[i / 4] = make_float4(r[0], r[1], r[2], r[3]);
    }
}

// ---------------------------------------------------------------------------
// Attention + fused epilogue. 1 query/thread; keys streamed through smem
// double buffer; no max tracking (scores bounded; constant shift cancels).
// ---------------------------------------------------------------------------
__global__ __launch_bounds__(TQ) void attn_kernel(const float* __restrict__ xin,
                                                  float* __restrict__ out) {
    __shared__ __align__(16) float Xs[2][TK * CIN];
    const int tid = threadIdx.x;
    const int b   = blockIdx.x >> 5;       // 32 q-tiles per batch
    const int qt  = blockIdx.x & 31;
    const int n   = qt * TQ + tid;
    const size_t g = (size_t)b * NPIX + n;

    ull r2[16];
    {
        const ulonglong2* qp = reinterpret_cast<const ulonglong2*>(g_Qt + g * CIN);
#pragma unroll
        for (int k = 0; k < 8; ++k) { ulonglong2 v = qp[k]; r2[2*k] = v.x; r2[2*k+1] = v.y; }
    }
    ull O2[16];
#pragma unroll
    for (int k = 0; k < 16; ++k) O2[k] = 0ull;
    float l = 0.f;

    const float* Xb = g_Xt + (size_t)b * NPIX * CIN;

    // prologue: tile 0 -> buf 0
#pragma unroll
    for (int k = 0; k < (TK * CIN / 4) / TQ; ++k) {
        int idx = 4 * (tid + k * TQ);
        cp_async16(&Xs[0][idx], Xb + idx);
    }
    cp_commit();

#pragma unroll 1
    for (int t = 0; t < NT; ++t) {
        if (t + 1 < NT) {
            const float* src = Xb + (size_t)(t + 1) * TK * CIN;
            float* dst = &Xs[(t + 1) & 1][0];
#pragma unroll
            for (int k = 0; k < (TK * CIN / 4) / TQ; ++k) {
                int idx = 4 * (tid + k * TQ);
                cp_async16(dst + idx, src + idx);
            }
            cp_commit();
            cp_wait<1>();
        } else {
            cp_wait<0>();
        }
        __syncthreads();
        const float* xs = Xs[t & 1];
#pragma unroll 4
        for (int j = 0; j < TK; ++j) {
            const ulonglong2* row = reinterpret_cast<const ulonglong2*>(xs + j * CIN);
            ull xv[16];
#pragma unroll
            for (int k = 0; k < 8; ++k) { ulonglong2 v = row[k]; xv[2*k] = v.x; xv[2*k+1] = v.y; }
            ull a0 = 0ull, a1 = 0ull, a2 = 0ull, a3 = 0ull;
#pragma unroll
            for (int k = 0; k < 4; ++k) {
                ffma2(a0, r2[4*k + 0], xv[4*k + 0]);
                ffma2(a1, r2[4*k + 1], xv[4*k + 1]);
                ffma2(a2, r2[4*k + 2], xv[4*k + 2]);
                ffma2(a3, r2[4*k + 3], xv[4*k + 3]);
            }
            fadd2(a0, a1); fadd2(a2, a3); fadd2(a0, a2);
            float2 sp = unpack2(a0);
            float arg = sp.x + sp.y - SHIFT;
            float p;
            asm("ex2.approx.f32 %0, %1;" : "=f"(p) : "f"(arg));
            l += p;
            ull p2 = pack1(p);
#pragma unroll
            for (int k = 0; k < 16; ++k) ffma2(O2[k], p2, xv[k]);
        }
        __syncthreads();
    }

    // normalize
    float inv;
    asm("rcp.approx.f32 %0, %1;" : "=f"(inv) : "f"(l));
    ull inv2 = pack1(inv);
    float ov[CIN];
#pragma unroll
    for (int k = 0; k < 16; ++k) {
        fmul2(O2[k], inv2);
        float2 v = unpack2(O2[k]);
        ov[2*k] = v.x; ov[2*k+1] = v.y;
    }

    // epilogue: y = WoWv * ov + b2 + x  (packed over output-channel pairs)
    ull y2[16];
    {
        const ulonglong2* bp = reinterpret_cast<const ulonglong2*>(g_b2);
#pragma unroll
        for (int k = 0; k < 8; ++k) { ulonglong2 v = bp[k]; y2[2*k] = v.x; y2[2*k+1] = v.y; }
    }
#pragma unroll 4
    for (int jj = 0; jj < CIN; ++jj) {
        ull pj = pack1(ov[jj]);
        const ulonglong2* wp = reinterpret_cast<const ulonglong2*>(g_WovP + jj * CIN);
#pragma unroll
        for (int k = 0; k < 8; ++k) {
            ulonglong2 w = wp[k];
            ffma2(y2[2*k],     pj, w.x);
            ffma2(y2[2*k + 1], pj, w.y);
        }
    }
    const float* xp = xin + (size_t)b * CIN * NPIX + n;
    float*       op = out + (size_t)b * CIN * NPIX + n;
#pragma unroll
    for (int k = 0; k < 16; ++k) {
        float2 y = unpack2(y2[k]);
        op[(size_t)(2*k)     * NPIX] = y.x + xp[(size_t)(2*k)     * NPIX];
        op[(size_t)(2*k + 1) * NPIX] = y.y + xp[(size_t)(2*k + 1) * NPIX];
    }
}

// ---------------------------------------------------------------------------
extern "C" void kernel_launch(void* const* d_in, const int* in_sizes, int n_in,
                              void* d_out, int out_size) {
    (void)in_sizes; (void)n_in; (void)out_size;
    const float* x  = (const float*)d_in[0];
    const float* wq = (const float*)d_in[1];
    const float* bq = (const float*)d_in[2];
    const float* wk = (const float*)d_in[3];
    // d_in[4] = bk: row-constant in softmax -> mathematically cancels, unused
    const float* wv = (const float*)d_in[5];
    const float* bv = (const float*)d_in[6];
    const float* wo = (const float*)d_in[7];
    const float* bo = (const float*)d_in[8];
    float* out = (float*)d_out;

    derive_kernel<<<1, 1024>>>(wq, bq, wk, wv, wo, bv, bo);
    transpose_kernel<<<dim3(NPIX / 32, BATCH), dim3(32, 32)>>>(x);
    qproj_kernel<<<(BATCH * NPIX) / TQ, TQ>>>();
    attn_kernel<<<BATCH * (NPIX / TQ), TQ>>>(x, out);
}

// round 5
// speedup vs baseline: 1.0605x; 1.0605x over previous
#include <cuda_runtime.h>
#include <cstdint>

// ---------------------------------------------------------------------------
// SAM spatial self-attention, algebraically reduced:
//   softmax scores: s_nm = r_n . x_m  with r_n = (Wq^T Wk)^T x_n + Wk^T bq
//   output:         y    = (Wo Wv) (attn . X)_n + (Wo bv + bo) + x_n
// R3: 2-way key-split per block (occupancy was grid/thread-count bound at
// 6.9 warps/SM); fused transpose+r-projection; one-wave launch geometry.
// ---------------------------------------------------------------------------

namespace {
constexpr int BATCH = 8;
constexpr int CIN   = 32;
constexpr int COUT  = 64;
constexpr int NPIX  = 4096;   // 64*64
constexpr int TQ    = 64;     // queries per block
constexpr int NTHR  = 128;    // 64 queries x 2 key-groups
constexpr int TK    = 128;    // keys per smem tile
constexpr int KH    = 64;     // keys per group per tile
constexpr int NT    = NPIX / TK;
constexpr float LOG2E = 1.4426950408889634f;
constexpr float SHIFT = 14.0f;  // uniform log2-shift; cancels in softmax
}

// scratch (allocation-free rule: __device__ globals)
__device__ __align__(16) float g_Xt[BATCH * NPIX * CIN];   // x transposed: [b][n][c]
__device__ __align__(16) float g_Qt[BATCH * NPIX * CIN];   // r-vectors (log2-scaled)
__device__ __align__(16) float g_At[CIN * CIN];            // j-major: [j][i] = log2e*(Wq^T Wk)^T[i][j]
__device__ __align__(16) float g_cv[CIN];                  // log2e * Wk^T bq
__device__ __align__(16) float g_WovP[CIN * CIN];          // [j][o] = (Wo Wv)[o][j]
__device__ __align__(16) float g_b2[CIN];                  // Wo bv + bo

using ull = unsigned long long;

__device__ __forceinline__ void ffma2(ull& d, ull a, ull b) {
    asm("fma.rn.f32x2 %0, %1, %2, %0;" : "+l"(d) : "l"(a), "l"(b));
}
__device__ __forceinline__ void fadd2(ull& d, ull b) {
    asm("add.rn.f32x2 %0, %0, %1;" : "+l"(d) : "l"(b));
}
__device__ __forceinline__ void fmul2(ull& d, ull b) {
    asm("mul.rn.f32x2 %0, %0, %1;" : "+l"(d) : "l"(b));
}
__device__ __forceinline__ ull pack1(float p) {
    ull r; asm("mov.b64 %0, {%1, %1};" : "=l"(r) : "f"(p)); return r;
}
__device__ __forceinline__ float2 unpack2(ull v) {
    float2 r; asm("mov.b64 {%0, %1}, %2;" : "=f"(r.x), "=f"(r.y) : "l"(v)); return r;
}
__device__ __forceinline__ void cp_async16(void* s, const void* g) {
    unsigned sa = (unsigned)__cvta_generic_to_shared(s);
    asm volatile("cp.async.cg.shared.global [%0], [%1], 16;" :: "r"(sa), "l"(g));
}
__device__ __forceinline__ void cp_commit() { asm volatile("cp.async.commit_group;"); }
template<int N> __device__ __forceinline__ void cp_wait() {
    asm volatile("cp.async.wait_group %0;" :: "n"(N));
}

// ---------------------------------------------------------------------------
// Derived weights (tiny; 1 block, 1024 threads)
// ---------------------------------------------------------------------------
__global__ void derive_kernel(const float* __restrict__ wq, const float* __restrict__ bq,
                              const float* __restrict__ wk, const float* __restrict__ wv,
                              const float* __restrict__ wo, const float* __restrict__ bv,
                              const float* __restrict__ bo) {
    int t = threadIdx.x;
    int i = t >> 5, j = t & 31;
    // At[i][j] = sum_o wk[o][i] * wq[o][j]; stored j-major for the fused matvec
    float a = 0.f;
    for (int o = 0; o < COUT; ++o) a += wk[o * CIN + i] * wq[o * CIN + j];
    g_At[j * CIN + i] = a * LOG2E;
    // WovP[i][j] = (Wo Wv)[j][i]
    float w = 0.f;
    for (int cc = 0; cc < COUT; ++cc) w += wo[j * COUT + cc] * wv[cc * CIN + i];
    g_WovP[i * CIN + j] = w;
    if (t < CIN) {
        float c = 0.f;
        for (int o = 0; o < COUT; ++o) c += bq[o] * wk[o * CIN + t];
        g_cv[t] = c * LOG2E;
        float b = bo[t];
        for (int cc = 0; cc < COUT; ++cc) b += wo[t * COUT + cc] * bv[cc];
        g_b2[t] = b;
    }
}

// ---------------------------------------------------------------------------
// Fused: transpose x (B,C,N)->Xt (B,N,C)  AND  r-projection Qt = At*x + cv
// (the 32x32 tile in smem already holds all channels of 32 pixels)
// ---------------------------------------------------------------------------
__global__ void tq_kernel(const float* __restrict__ x) {
    __shared__ float s[CIN][33];
    __shared__ float sA[CIN * CIN];
    __shared__ float scv[CIN];
    int b  = blockIdx.y;
    int n0 = blockIdx.x * 32;
    int tx = threadIdx.x, ty = threadIdx.y;
    int t  = ty * 32 + tx;
    sA[t] = g_At[t];
    if (t < CIN) scv[t] = g_cv[t];
    s[ty][tx] = x[((size_t)b * CIN + ty) * NPIX + n0 + tx];   // s[chan][pix]
    __syncthreads();
    // Xt write: pixel = ty, chan = tx
    g_Xt[((size_t)b * NPIX + n0 + ty) * CIN + tx] = s[tx][ty];
    // Qt: pixel = ty, out-channel i = tx
    float acc = scv[tx];
#pragma unroll
    for (int j = 0; j < CIN; ++j) acc += sA[j * CIN + tx] * s[j][ty];
    g_Qt[((size_t)b * NPIX + n0 + ty) * CIN + tx] = acc;
}

// ---------------------------------------------------------------------------
// Attention + fused epilogue.
// Block: 128 threads = 64 queries x 2 key-groups sharing smem key tiles.
// Group g handles keys [64g, 64g+64) of each 128-key tile; partial (O, l)
// combined via smem (softmax denominators add exactly).
// ---------------------------------------------------------------------------
__global__ __launch_bounds__(NTHR, 4) void attn_kernel(const float* __restrict__ xin,
                                                       float* __restrict__ out) {
    __shared__ __align__(16) float Xs[2][TK * CIN];   // 32 KB
    __shared__ float sO[CIN][TQ];                     // 8 KB (combine buffer)
    __shared__ float sL[TQ];

    const int tid = threadIdx.x;
    const int grp = tid >> 6;            // key-group 0/1
    const int lq  = tid & 63;            // local query
    const int b   = blockIdx.x >> 6;     // 64 q-tiles per batch
    const int qt  = blockIdx.x & 63;
    const int n   = qt * TQ + lq;
    const size_t g = (size_t)b * NPIX + n;

    ull r2[16];
    {
        const ulonglong2* qp = reinterpret_cast<const ulonglong2*>(g_Qt + g * CIN);
#pragma unroll
        for (int k = 0; k < 8; ++k) { ulonglong2 v = qp[k]; r2[2*k] = v.x; r2[2*k+1] = v.y; }
    }
    ull O2[16];
#pragma unroll
    for (int k = 0; k < 16; ++k) O2[k] = 0ull;
    float l = 0.f;

    const float* Xb = g_Xt + (size_t)b * NPIX * CIN;

    // prologue: tile 0 -> buf 0 (all 128 threads cooperate: 8 x 16B each)
#pragma unroll
    for (int k = 0; k < (TK * CIN / 4) / NTHR; ++k) {
        int idx = 4 * (tid + k * NTHR);
        cp_async16(&Xs[0][idx], Xb + idx);
    }
    cp_commit();

#pragma unroll 1
    for (int t = 0; t < NT; ++t) {
        if (t + 1 < NT) {
            const float* src = Xb + (size_t)(t + 1) * TK * CIN;
            float* dst = &Xs[(t + 1) & 1][0];
#pragma unroll
            for (int k = 0; k < (TK * CIN / 4) / NTHR; ++k) {
                int idx = 4 * (tid + k * NTHR);
                cp_async16(dst + idx, src + idx);
            }
            cp_commit();
            cp_wait<1>();
        } else {
            cp_wait<0>();
        }
        __syncthreads();
        const float* xs = &Xs[t & 1][0] + grp * (KH * CIN);
#pragma unroll 4
        for (int j = 0; j < KH; ++j) {
            const ulonglong2* row = reinterpret_cast<const ulonglong2*>(xs + j * CIN);
            ull xv[16];
#pragma unroll
            for (int k = 0; k < 8; ++k) { ulonglong2 v = row[k]; xv[2*k] = v.x; xv[2*k+1] = v.y; }
            ull a0 = 0ull, a1 = 0ull, a2 = 0ull, a3 = 0ull;
#pragma unroll
            for (int k = 0; k < 4; ++k) {
                ffma2(a0, r2[4*k + 0], xv[4*k + 0]);
                ffma2(a1, r2[4*k + 1], xv[4*k + 1]);
                ffma2(a2, r2[4*k + 2], xv[4*k + 2]);
                ffma2(a3, r2[4*k + 3], xv[4*k + 3]);
            }
            fadd2(a0, a1); fadd2(a2, a3); fadd2(a0, a2);
            float2 sp = unpack2(a0);
            float arg = (sp.x + sp.y) - SHIFT;
            float p;
            asm("ex2.approx.f32 %0, %1;" : "=f"(p) : "f"(arg));
            l += p;
            ull p2 = pack1(p);
#pragma unroll
            for (int k = 0; k < 16; ++k) ffma2(O2[k], p2, xv[k]);
        }
        __syncthreads();
    }

    // ---- combine the two key-groups via smem ----
    if (grp == 1) {
#pragma unroll
        for (int k = 0; k < 16; ++k) {
            float2 v = unpack2(O2[k]);
            sO[2*k][lq]     = v.x;
            sO[2*k + 1][lq] = v.y;
        }
        sL[lq] = l;
    }
    __syncthreads();
    if (grp == 0) {
        l += sL[lq];
        float inv;
        asm("rcp.approx.f32 %0, %1;" : "=f"(inv) : "f"(l));
        float ov[CIN];
#pragma unroll
        for (int k = 0; k < 16; ++k) {
            float2 v = unpack2(O2[k]);
            ov[2*k]     = (v.x + sO[2*k][lq])     * inv;
            ov[2*k + 1] = (v.y + sO[2*k + 1][lq]) * inv;
        }

        // epilogue: y = WoWv * ov + b2 + x
        ull y2[16];
        {
            const ulonglong2* bp = reinterpret_cast<const ulonglong2*>(g_b2);
#pragma unroll
            for (int k = 0; k < 8; ++k) { ulonglong2 v = bp[k]; y2[2*k] = v.x; y2[2*k+1] = v.y; }
        }
#pragma unroll 4
        for (int jj = 0; jj < CIN; ++jj) {
            ull pj = pack1(ov[jj]);
            const ulonglong2* wp = reinterpret_cast<const ulonglong2*>(g_WovP + jj * CIN);
#pragma unroll
            for (int k = 0; k < 8; ++k) {
                ulonglong2 w = wp[k];
                ffma2(y2[2*k],     pj, w.x);
                ffma2(y2[2*k + 1], pj, w.y);
            }
        }
        const float* xp = xin + (size_t)b * CIN * NPIX + n;
        float*       op = out + (size_t)b * CIN * NPIX + n;
#pragma unroll
        for (int k = 0; k < 16; ++k) {
            float2 y = unpack2(y2[k]);
            op[(size_t)(2*k)     * NPIX] = y.x + xp[(size_t)(2*k)     * NPIX];
            op[(size_t)(2*k + 1) * NPIX] = y.y + xp[(size_t)(2*k + 1) * NPIX];
        }
    }
}

// ---------------------------------------------------------------------------
extern "C" void kernel_launch(void* const* d_in, const int* in_sizes, int n_in,
                              void* d_out, int out_size) {
    (void)in_sizes; (void)n_in; (void)out_size;
    const float* x  = (const float*)d_in[0];
    const float* wq = (const float*)d_in[1];
    const float* bq = (const float*)d_in[2];
    const float* wk = (const float*)d_in[3];
    // d_in[4] = bk: row-constant in softmax -> cancels, unused
    const float* wv = (const float*)d_in[5];
    const float* bv = (const float*)d_in[6];
    const float* wo = (const float*)d_in[7];
    const float* bo = (const float*)d_in[8];
    float* out = (float*)d_out;

    derive_kernel<<<1, 1024>>>(wq, bq, wk, wv, wo, bv, bo);
    tq_kernel<<<dim3(NPIX / 32, BATCH), dim3(32, 32)>>>(x);
    attn_kernel<<<BATCH * (NPIX / TQ), NTHR>>>(x, out);
}

// round 7
// speedup vs baseline: 3.5516x; 3.3490x over previous
#include <cuda_runtime.h>
#include <cuda_bf16.h>
#include <cstdint>

// ---------------------------------------------------------------------------
// SAM spatial self-attention, reduced algebra + HMMA (mma.sync bf16) flash.
//   scores: s_nm = r_n . x_m,  r = log2e*((Wq^T Wk)^T x + Wk^T bq)
//   out:    y = (Wo Wv)(softmax(s) X) + (Wo bv + bo) + x
// bf16 2-way splits, 3 of 4 cross products kept (QK, and PV).
// tcgen05 is unavailable (harness compiles via compute_103, no 'a' features),
// so tensor work goes through mma.sync.m16n8k16 (sm_80 baseline PTX).
// ---------------------------------------------------------------------------

namespace {
constexpr int BATCH = 8, CIN = 32, COUT = 64, NPIX = 4096;
constexpr int MQ  = 128;           // queries per CTA
constexpr int TK  = 64;            // keys per tile
constexpr int NKT = NPIX / TK;     // 64
constexpr float LOG2E = 1.4426950408889634f;
constexpr float SHIFT = 14.0f;     // folded into S accumulator init
// image geometry (bytes). K rows padded 64->80B, V rows 128->144B for
// conflict-free B-fragment LDS (bank sets {20tg+l} / {4tg+8k+l} are distinct).
constexpr int KROW_B = 80;                    // 16 data words + 4 pad
constexpr int KIMG_B = 2 * TK * KROW_B;       // 10240 (2 splits)
constexpr int VROW_B = 144;                   // 32 data words + 4 pad
constexpr int VIMG_B = 2 * CIN * VROW_B;      // 9216  (2 splits)
// smem layout (attn)
constexpr int SM_K  = 0;                      // 2 x 10240
constexpr int SM_V  = 2 * KIMG_B;             // 20480: 2 x 9216
constexpr int SM_W  = SM_V + 2 * VIMG_B;      // 38912: WovP 4096B
constexpr int SM_B2 = SM_W + 4096;            // 43008: 128B
constexpr int SM_OV = SM_B2 + 128;            // 43136: 128*33*4 = 16896
constexpr int SM_TOTAL = SM_OV + 128 * 33 * 4; // 60032
}

// global scratch (allocation-free rule)
__device__ __align__(16) float g_At[CIN * CIN];    // [j][i] = log2e*(Wq^T Wk)[i][j]
__device__ __align__(16) float g_cv[CIN];
__device__ __align__(16) float g_WovP[CIN * CIN];  // [j][c] = (Wo Wv)[c][j]
__device__ __align__(16) float g_b2[CIN];
__device__ __align__(16) unsigned char g_Kimg[BATCH * NKT * KIMG_B]; // 5.24MB
__device__ __align__(16) unsigned char g_Vimg[BATCH * NKT * VIMG_B]; // 4.72MB
__device__ __align__(16) uint32_t g_Rw[2 * BATCH * NPIX * 16];       // 4MB

// ---------------- helpers ----------------
__device__ __forceinline__ void mma_bf16(float* d, const uint32_t* a, const uint32_t* b) {
    asm("mma.sync.aligned.m16n8k16.row.col.f32.bf16.bf16.f32 "
        "{%0,%1,%2,%3}, {%4,%5,%6,%7}, {%8,%9}, {%0,%1,%2,%3};"
        : "+f"(d[0]), "+f"(d[1]), "+f"(d[2]), "+f"(d[3])
        : "r"(a[0]), "r"(a[1]), "r"(a[2]), "r"(a[3]), "r"(b[0]), "r"(b[1]));
}
__device__ __forceinline__ uint32_t pk_bf(float lo, float hi) {   // {hi:lo} packed
    uint32_t r;
    asm("cvt.rn.satfinite.bf16x2.f32 %0, %1, %2;" : "=r"(r) : "f"(hi), "f"(lo));
    return r;
}
__device__ __forceinline__ float ex2f(float a) {
    float p; asm("ex2.approx.f32 %0, %1;" : "=f"(p) : "f"(a)); return p;
}
__device__ __forceinline__ uint32_t sm_u32(const void* p) {
    uint32_t a;
    asm("{ .reg .u64 t; cvta.to.shared.u64 t, %1; cvt.u32.u64 %0, t; }" : "=r"(a) : "l"(p));
    return a;
}
__device__ __forceinline__ void cp16(uint32_t s, const void* g) {
    asm volatile("cp.async.cg.shared.global [%0], [%1], 16;" :: "r"(s), "l"(g));
}
__device__ __forceinline__ void cp_commit() { asm volatile("cp.async.commit_group;"); }
template<int N> __device__ __forceinline__ void cp_wait() {
    asm volatile("cp.async.wait_group %0;" :: "n"(N));
}

// ---------------------------------------------------------------------------
// Derived weights (parallelized)
// ---------------------------------------------------------------------------
__global__ void derive_kernel(const float* __restrict__ wq, const float* __restrict__ bq,
                              const float* __restrict__ wk, const float* __restrict__ wv,
                              const float* __restrict__ wo, const float* __restrict__ bv,
                              const float* __restrict__ bo) {
    int g = blockIdx.x * 128 + threadIdx.x;
    if (g < 1024) {
        int i = g >> 5, j = g & 31;
        float a = 0.f;
#pragma unroll 8
        for (int o = 0; o < COUT; ++o) a += wk[o * CIN + i] * wq[o * CIN + j];
        g_At[j * CIN + i] = a * LOG2E;
    } else if (g < 2048) {
        int t = g - 1024, i = t >> 5, j = t & 31;
        float w = 0.f;
#pragma unroll 8
        for (int cc = 0; cc < COUT; ++cc) w += wo[j * COUT + cc] * wv[cc * CIN + i];
        g_WovP[i * CIN + j] = w;
    } else if (g < 2080) {
        int t = g - 2048;
        float c = 0.f;
        for (int o = 0; o < COUT; ++o) c += bq[o] * wk[o * CIN + t];
        g_cv[t] = c * LOG2E;
    } else if (g < 2112) {
        int t = g - 2080;
        float b = bo[t];
        for (int cc = 0; cc < COUT; ++cc) b += wo[t * COUT + cc] * bv[cc];
        g_b2[t] = b;
    }
}

// ---------------------------------------------------------------------------
// Precursor: r-projection + bf16-split images (K rows, V rows, R words).
// One thread = one pixel. grid (16, 8), 256 threads.
// ---------------------------------------------------------------------------
__global__ void tq_kernel(const float* __restrict__ x) {
    __shared__ float sA[CIN * CIN];
    __shared__ float scv[CIN];
    int tid = threadIdx.x;
    int b = blockIdx.y;
    int n = blockIdx.x * 256 + tid;
    for (int i = tid; i < CIN * CIN; i += 256) sA[i] = g_At[i];
    if (tid < CIN) scv[tid] = g_cv[tid];
    __syncthreads();

    float xv[CIN];
#pragma unroll
    for (int c = 0; c < CIN; ++c) xv[c] = x[((size_t)b * CIN + c) * NPIX + n];
    float r[CIN];
#pragma unroll
    for (int i = 0; i < CIN; ++i) r[i] = scv[i];
#pragma unroll
    for (int j = 0; j < CIN; ++j) {
        float v = xv[j];
#pragma unroll
        for (int i = 0; i < CIN; ++i) r[i] += sA[j * CIN + i] * v;
    }

    int kt = n >> 6, kl = n & 63;
    // K image rows (split0 then split1)
    uint32_t* K0 = (uint32_t*)(g_Kimg + (size_t)(b * NKT + kt) * KIMG_B) + kl * 20;
    uint32_t* K1 = K0 + TK * 20;
    // V image (row = channel, col = key)
    unsigned char* V0 = g_Vimg + (size_t)(b * NKT + kt) * VIMG_B;
    unsigned char* V1 = V0 + CIN * VROW_B;
    // R words
    uint32_t* R0 = g_Rw + ((size_t)b * NPIX + n) * 16;
    uint32_t* R1 = R0 + (size_t)BATCH * NPIX * 16;

#pragma unroll
    for (int w = 0; w < 16; ++w) {
        float va = xv[2 * w], vb = xv[2 * w + 1];
        __nv_bfloat16 a1 = __float2bfloat16(va), b1 = __float2bfloat16(vb);
        float a1f = __bfloat162float(a1), b1f = __bfloat162float(b1);
        K0[w] = pk_bf(a1f, b1f);                       // exact bf16 re-pack
        K1[w] = pk_bf(va - a1f, vb - b1f);
        float ra = r[2 * w], rb = r[2 * w + 1];
        __nv_bfloat16 c1 = __float2bfloat16(ra), d1 = __float2bfloat16(rb);
        float c1f = __bfloat162float(c1), d1f = __bfloat162float(d1);
        R0[w] = pk_bf(c1f, d1f);
        R1[w] = pk_bf(ra - c1f, rb - d1f);
    }
    K0[16] = K0[17] = K0[18] = K0[19] = 0u;
    K1[16] = K1[17] = K1[18] = K1[19] = 0u;
#pragma unroll
    for (int c = 0; c < CIN; ++c) {
        float v = xv[c];
        __nv_bfloat16 h1 = __float2bfloat16(v);
        *(__nv_bfloat16*)(V0 + c * VROW_B + kl * 2) = h1;
        *(__nv_bfloat16*)(V1 + c * VROW_B + kl * 2) =
            __float2bfloat16(v - __bfloat162float(h1));
    }
}

// ---------------------------------------------------------------------------
// HMMA flash attention. 128 threads = 4 warps x 32 query rows.
// ---------------------------------------------------------------------------
__global__ __launch_bounds__(128, 2) void attn_kernel(const float* __restrict__ xin,
                                                      float* __restrict__ out) {
    extern __shared__ unsigned char sm[];
    const int tid  = threadIdx.x, wid = tid >> 5, lane = tid & 31;
    const int tg   = lane >> 2, la = lane & 3;
    const int b    = blockIdx.x >> 5, qt = blockIdx.x & 31;
    const uint32_t smb = sm_u32(sm);

    float* sW  = (float*)(sm + SM_W);
    float* sB2 = (float*)(sm + SM_B2);
    float* sOv = (float*)(sm + SM_OV);
    for (int i = tid; i < CIN * CIN; i += 128) sW[i] = g_WovP[i];
    if (tid < CIN) sB2[tid] = g_b2[tid];

    // R fragments (resident): Ra[split][m][kblk][4]
    uint32_t Ra[2][2][2][4];
#pragma unroll
    for (int s = 0; s < 2; ++s)
#pragma unroll
        for (int m = 0; m < 2; ++m) {
            int qr = qt * MQ + 32 * wid + 16 * m + tg;
            const uint32_t* p0 = g_Rw + (((size_t)s * BATCH + b) * NPIX + qr) * 16;
            const uint32_t* p8 = p0 + 8 * 16;
#pragma unroll
            for (int k = 0; k < 2; ++k) {
                Ra[s][m][k][0] = p0[8 * k + la];
                Ra[s][m][k][1] = p8[8 * k + la];
                Ra[s][m][k][2] = p0[8 * k + la + 4];
                Ra[s][m][k][3] = p8[8 * k + la + 4];
            }
        }

    float O[2][4][4];
#pragma unroll
    for (int m = 0; m < 2; ++m)
#pragma unroll
        for (int c = 0; c < 4; ++c)
#pragma unroll
            for (int e = 0; e < 4; ++e) O[m][c][e] = 0.f;
    float l4[4] = {0.f, 0.f, 0.f, 0.f};

    // stage tile 0
    {
        const uint4* Ks = (const uint4*)(g_Kimg + (size_t)(b * NKT + 0) * KIMG_B);
        const uint4* Vs = (const uint4*)(g_Vimg + (size_t)(b * NKT + 0) * VIMG_B);
#pragma unroll
        for (int i = tid; i < KIMG_B / 16; i += 128) cp16(smb + SM_K + i * 16, Ks + i);
#pragma unroll
        for (int i = tid; i < VIMG_B / 16; i += 128) cp16(smb + SM_V + i * 16, Vs + i);
        cp_commit();
    }

#pragma unroll 1
    for (int t = 0; t < NKT; ++t) {
        if (t + 1 < NKT) {
            int nb = (t + 1) & 1;
            const uint4* Ks = (const uint4*)(g_Kimg + (size_t)(b * NKT + t + 1) * KIMG_B);
            const uint4* Vs = (const uint4*)(g_Vimg + (size_t)(b * NKT + t + 1) * VIMG_B);
#pragma unroll
            for (int i = tid; i < KIMG_B / 16; i += 128)
                cp16(smb + SM_K + nb * KIMG_B + i * 16, Ks + i);
#pragma unroll
            for (int i = tid; i < VIMG_B / 16; i += 128)
                cp16(smb + SM_V + nb * VIMG_B + i * 16, Vs + i);
            cp_commit();
            cp_wait<1>();
        } else {
            cp_wait<0>();
        }
        __syncthreads();
        const unsigned char* kb = sm + SM_K + (t & 1) * KIMG_B;
        const unsigned char* vb = sm + SM_V + (t & 1) * VIMG_B;

        // ---- QK: S[2m][8j][4] = R.K^T - SHIFT ----
        float S[2][8][4];
#pragma unroll
        for (int m = 0; m < 2; ++m)
#pragma unroll
            for (int j = 0; j < 8; ++j)
#pragma unroll
                for (int e = 0; e < 4; ++e) S[m][j][e] = -SHIFT;

#pragma unroll
        for (int bs = 0; bs < 2; ++bs) {
            uint32_t Bf[8][2][2];
#pragma unroll
            for (int j = 0; j < 8; ++j)
#pragma unroll
                for (int k = 0; k < 2; ++k) {
                    int off = bs * (TK * KROW_B) + ((8 * j + tg) * 20 + 8 * k + la) * 4;
                    Bf[j][k][0] = *(const uint32_t*)(kb + off);
                    Bf[j][k][1] = *(const uint32_t*)(kb + off + 16);
                }
            const int nas = bs ? 1 : 2;   // products: (R1,K1),(R2,K1),(R1,K2)
            for (int as = 0; as < nas; ++as)
#pragma unroll
                for (int m = 0; m < 2; ++m)
#pragma unroll
                    for (int j = 0; j < 8; ++j)
#pragma unroll
                        for (int k = 0; k < 2; ++k)
                            mma_bf16(S[m][j], Ra[as][m][k], Bf[j][k]);
        }

        // ---- softmax -> P1,P2 bf16 fragments (register reinterpret) ----
        uint32_t P1[2][4][4], P2[2][4][4];
#pragma unroll
        for (int m = 0; m < 2; ++m)
#pragma unroll
            for (int j = 0; j < 8; ++j) {
                float p0 = ex2f(S[m][j][0]), p1 = ex2f(S[m][j][1]);
                float p2 = ex2f(S[m][j][2]), p3 = ex2f(S[m][j][3]);
                l4[2 * m]     += p0 + p1;
                l4[2 * m + 1] += p2 + p3;
                int kk = j >> 1, o = (j & 1) * 2;
                uint32_t q0 = pk_bf(p0, p1), q1 = pk_bf(p2, p3);
                P1[m][kk][o]     = q0;
                P1[m][kk][o + 1] = q1;
                P2[m][kk][o]     = pk_bf(p0 - __uint_as_float(q0 << 16),
                                         p1 - __uint_as_float(q0 & 0xFFFF0000u));
                P2[m][kk][o + 1] = pk_bf(p2 - __uint_as_float(q1 << 16),
                                         p3 - __uint_as_float(q1 & 0xFFFF0000u));
            }

        // ---- PV: O += P.V (products: (P1,V1),(P2,V1),(P1,V2)) ----
#pragma unroll
        for (int vs = 0; vs < 2; ++vs) {
            uint32_t Vf[4][4][2];
#pragma unroll
            for (int c = 0; c < 4; ++c)
#pragma unroll
                for (int k = 0; k < 4; ++k) {
                    int off = vs * (CIN * VROW_B) + (8 * c + tg) * VROW_B + (8 * k + la) * 4;
                    Vf[c][k][0] = *(const uint32_t*)(vb + off);
                    Vf[c][k][1] = *(const uint32_t*)(vb + off + 16);
                }
            const int nps = vs ? 1 : 2;
            for (int ps = 0; ps < nps; ++ps)
#pragma unroll
                for (int m = 0; m < 2; ++m)
#pragma unroll
                    for (int c = 0; c < 4; ++c)
#pragma unroll
                        for (int k = 0; k < 4; ++k)
                            mma_bf16(O[m][c], ps ? P2[m][k] : P1[m][k], Vf[c][k]);
        }
        __syncthreads();
    }

    // ---- epilogue: l reduce (across la), normalize, store ov to smem ----
#pragma unroll
    for (int i = 0; i < 4; ++i) {
        l4[i] += __shfl_xor_sync(0xFFFFFFFFu, l4[i], 1);
        l4[i] += __shfl_xor_sync(0xFFFFFFFFu, l4[i], 2);
        asm("rcp.approx.f32 %0, %1;" : "+f"(l4[i]) : "f"(l4[i]));
    }
#pragma unroll
    for (int m = 0; m < 2; ++m)
#pragma unroll
        for (int h = 0; h < 2; ++h) {
            int row = 32 * wid + 16 * m + 8 * h + tg;
            float inv = l4[2 * m + h];
#pragma unroll
            for (int c = 0; c < 4; ++c) {
                sOv[row * 33 + 8 * c + 2 * la]     = O[m][c][2 * h]     * inv;
                sOv[row * 33 + 8 * c + 2 * la + 1] = O[m][c][2 * h + 1] * inv;
            }
        }
    __syncthreads();

    // ---- fused projection + bias + residual (1 query/thread) ----
    float ov[CIN], y[CIN];
#pragma unroll
    for (int c = 0; c < CIN; ++c) ov[c] = sOv[tid * 33 + c];
#pragma unroll
    for (int c = 0; c < CIN; ++c) y[c] = sB2[c];
#pragma unroll 4
    for (int j = 0; j < CIN; ++j) {
        float pj = ov[j];
        const float* wp = sW + j * CIN;
#pragma unroll
        for (int c = 0; c < CIN; ++c) y[c] += pj * wp[c];
    }
    int n = qt * MQ + tid;
    const float* xp = xin + (size_t)b * CIN * NPIX + n;
    float*       op = out + (size_t)b * CIN * NPIX + n;
#pragma unroll
    for (int c = 0; c < CIN; ++c)
        op[(size_t)c * NPIX] = y[c] + xp[(size_t)c * NPIX];
}

// ---------------------------------------------------------------------------
extern "C" void kernel_launch(void* const* d_in, const int* in_sizes, int n_in,
                              void* d_out, int out_size) {
    (void)in_sizes; (void)n_in; (void)out_size;
    const float* x  = (const float*)d_in[0];
    const float* wq = (const float*)d_in[1];
    const float* bq = (const float*)d_in[2];
    const float* wk = (const float*)d_in[3];
    // d_in[4] = bk: cancels in softmax, unused
    const float* wv = (const float*)d_in[5];
    const float* bv = (const float*)d_in[6];
    const float* wo = (const float*)d_in[7];
    const float* bo = (const float*)d_in[8];
    float* out = (float*)d_out;

    cudaFuncSetAttribute(attn_kernel, cudaFuncAttributeMaxDynamicSharedMemorySize, SM_TOTAL);

    derive_kernel<<<17, 128>>>(wq, bq, wk, wv, wo, bv, bo);
    tq_kernel<<<dim3(NPIX / 256, BATCH), 256>>>(x);
    attn_kernel<<<BATCH * (NPIX / MQ), 128, SM_TOTAL>>>(x, out);
}

// round 9
// speedup vs baseline: 4.7717x; 1.3435x over previous
#include <cuda_runtime.h>
#include <cuda_bf16.h>
#include <cuda_fp16.h>
#include <cstdint>

// ---------------------------------------------------------------------------
// SAM spatial self-attention, reduced algebra + HMMA (mma.sync) flash.
//   scores: s_nm = r_n . x_m,  r = log2e*((Wq^T Wk)^T x + Wk^T bq)
//   out:    y = (Wo Wv)(softmax(s) X) + (Wo bv + bo) + x
// QK: bf16 2-way splits, 3 of 4 cross products.
// PV: single fp16 product. fp16 P overflow is prevented by a PROVABLE
// per-query shift: s <= ||r_n|| * max_m ||x_m|| (Cauchy-Schwarz), so
// p' = 2^(s - bound_n + 14) <= 2^14 < fp16 max. Softmax is invariant to
// any per-row constant, so this is exact.
// ---------------------------------------------------------------------------

namespace {
constexpr int BATCH = 8, CIN = 32, COUT = 64, NPIX = 4096;
constexpr int MQ  = 128;           // queries per CTA
constexpr int TK  = 64;            // keys per tile
constexpr int NKT = NPIX / TK;     // 64
constexpr float LOG2E = 1.4426950408889634f;
constexpr float OFF   = 14.0f;     // p' <= 2^14 (fp16-safe)
// image geometry (bytes). K rows padded 64->80B, V rows 128->144B for
// conflict-free B-fragment LDS.
constexpr int KROW_B = 80;                    // 16 data words + 4 pad
constexpr int KIMG_B = 2 * TK * KROW_B;       // 10240 (2 bf16 splits)
constexpr int VROW_B = 144;                   // 32 data words + 4 pad
constexpr int VIMG_B = CIN * VROW_B;          // 4608 (single fp16 image)
// smem layout (attn)
constexpr int SM_K  = 0;                      // 2 x 10240
constexpr int SM_V  = 2 * KIMG_B;             // 20480: 2 x 4608
constexpr int SM_W  = SM_V + 2 * VIMG_B;      // 29696: WovP 4096B
constexpr int SM_B2 = SM_W + 4096;            // 33792: 128B
constexpr int SM_OV = SM_B2 + 128;            // 33920: 128*33*4
constexpr int SM_TOTAL = SM_OV + 128 * 33 * 4; // 50816
}

// global scratch (allocation-free rule)
__device__ __align__(16) float g_At[CIN * CIN];    // [j][i] = log2e*(Wq^T Wk)[i][j]
__device__ __align__(16) float g_cv[CIN];
__device__ __align__(16) float g_WovP[CIN * CIN];  // [j][c] = (Wo Wv)[c][j]
__device__ __align__(16) float g_b2[CIN];
__device__ __align__(16) unsigned char g_Kimg[BATCH * NKT * KIMG_B]; // 5.24MB
__device__ __align__(16) unsigned char g_Vimg[BATCH * NKT * VIMG_B]; // 2.36MB
__device__ __align__(16) uint32_t g_Rw[2 * BATCH * NPIX * 16];       // 4MB
__device__ float    g_rn[BATCH * NPIX];            // ||r_n|| (log2e-scaled)
__device__ unsigned g_M2[BATCH];                   // bits of max ||x||^2

// ---------------- helpers ----------------
__device__ __forceinline__ void mma_bf16(float* d, const uint32_t* a, const uint32_t* b) {
    asm("mma.sync.aligned.m16n8k16.row.col.f32.bf16.bf16.f32 "
        "{%0,%1,%2,%3}, {%4,%5,%6,%7}, {%8,%9}, {%0,%1,%2,%3};"
        : "+f"(d[0]), "+f"(d[1]), "+f"(d[2]), "+f"(d[3])
        : "r"(a[0]), "r"(a[1]), "r"(a[2]), "r"(a[3]), "r"(b[0]), "r"(b[1]));
}
__device__ __forceinline__ void mma_f16(float* d, const uint32_t* a, const uint32_t* b) {
    asm("mma.sync.aligned.m16n8k16.row.col.f32.f16.f16.f32 "
        "{%0,%1,%2,%3}, {%4,%5,%6,%7}, {%8,%9}, {%0,%1,%2,%3};"
        : "+f"(d[0]), "+f"(d[1]), "+f"(d[2]), "+f"(d[3])
        : "r"(a[0]), "r"(a[1]), "r"(a[2]), "r"(a[3]), "r"(b[0]), "r"(b[1]));
}
__device__ __forceinline__ uint32_t pk_bf(float lo, float hi) {   // {hi:lo}
    uint32_t r;
    asm("cvt.rn.satfinite.bf16x2.f32 %0, %1, %2;" : "=r"(r) : "f"(hi), "f"(lo));
    return r;
}
__device__ __forceinline__ uint32_t pk_f16(float lo, float hi) {  // {hi:lo}
    uint32_t r;
    asm("cvt.rn.f16x2.f32 %0, %1, %2;" : "=r"(r) : "f"(hi), "f"(lo));
    return r;
}
__device__ __forceinline__ float ex2f(float a) {
    float p; asm("ex2.approx.f32 %0, %1;" : "=f"(p) : "f"(a)); return p;
}
__device__ __forceinline__ uint32_t sm_u32(const void* p) {
    uint32_t a;
    asm("{ .reg .u64 t; cvta.to.shared.u64 t, %1; cvt.u32.u64 %0, t; }" : "=r"(a) : "l"(p));
    return a;
}
__device__ __forceinline__ void cp16(uint32_t s, const void* g) {
    asm volatile("cp.async.cg.shared.global [%0], [%1], 16;" :: "r"(s), "l"(g));
}
__device__ __forceinline__ void cp_commit() { asm volatile("cp.async.commit_group;"); }
template<int N> __device__ __forceinline__ void cp_wait() {
    asm volatile("cp.async.wait_group %0;" :: "n"(N));
}

// ---------------------------------------------------------------------------
// Derived weights: 2 blocks x 1024 threads, smem-staged
// ---------------------------------------------------------------------------
__global__ void derive_kernel(const float* __restrict__ wq, const float* __restrict__ bq,
                              const float* __restrict__ wk, const float* __restrict__ wv,
                              const float* __restrict__ wo, const float* __restrict__ bv,
                              const float* __restrict__ bo) {
    __shared__ float sa[2048], sb[2048];
    int t = threadIdx.x;
    if (blockIdx.x == 0) {
        if (t < BATCH) g_M2[t] = 0u;                  // reset per launch (graph replay!)
        sa[t] = wk[t]; sa[t + 1024] = wk[t + 1024];   // wk [64][32]
        sb[t] = wq[t]; sb[t + 1024] = wq[t + 1024];   // wq [64][32]
        __syncthreads();
        int j = t >> 5, i = t & 31;
        float a = 0.f;
#pragma unroll
        for (int o = 0; o < COUT; ++o) a += sa[o * 32 + i] * sb[o * 32 + j];
        g_At[j * 32 + i] = a * LOG2E;
        if (t < 32) {
            float c = 0.f;
#pragma unroll
            for (int o = 0; o < COUT; ++o) c += bq[o] * sa[o * 32 + t];
            g_cv[t] = c * LOG2E;
        }
    } else {
        sa[t] = wv[t]; sa[t + 1024] = wv[t + 1024];   // wv [64][32]
        sb[t] = wo[t]; sb[t + 1024] = wo[t + 1024];   // wo [32][64]
        __syncthreads();
        int j = t >> 5, i = t & 31;
        float w = 0.f;
#pragma unroll
        for (int cc = 0; cc < COUT; ++cc) w += sb[j * 64 + cc] * sa[cc * 32 + i];
        g_WovP[i * 32 + j] = w;
        if (t < 32) {
            float b = bo[t];
#pragma unroll
            for (int cc = 0; cc < COUT; ++cc) b += sb[t * 64 + cc] * bv[cc];
            g_b2[t] = b;
        }
    }
}

// ---------------------------------------------------------------------------
// Precursor: r-projection + images + norms (||r_n||, max ||x||^2 per batch).
// ---------------------------------------------------------------------------
__global__ void tq_kernel(const float* __restrict__ x) {
    __shared__ float sA[CIN * CIN];
    __shared__ float scv[CIN];
    int tid = threadIdx.x;
    int b = blockIdx.y;
    int n = blockIdx.x * 256 + tid;
    for (int i = tid; i < CIN * CIN; i += 256) sA[i] = g_At[i];
    if (tid < CIN) scv[tid] = g_cv[tid];
    __syncthreads();

    float xv[CIN];
#pragma unroll
    for (int c = 0; c < CIN; ++c) xv[c] = x[((size_t)b * CIN + c) * NPIX + n];
    float r[CIN];
#pragma unroll
    for (int i = 0; i < CIN; ++i) r[i] = scv[i];
#pragma unroll
    for (int j = 0; j < CIN; ++j) {
        float v = xv[j];
#pragma unroll
        for (int i = 0; i < CIN; ++i) r[i] += sA[j * CIN + i] * v;
    }

    // norms for the provable softmax shift
    float nx2 = 0.f, nr2 = 0.f;
#pragma unroll
    for (int c = 0; c < CIN; ++c) { nx2 += xv[c] * xv[c]; nr2 += r[c] * r[c]; }
    atomicMax(&g_M2[b], __float_as_uint(nx2));        // positive floats: uint order
    g_rn[(size_t)b * NPIX + n] = sqrtf(nr2);

    int kt = n >> 6, kl = n & 63;
    uint32_t* K0 = (uint32_t*)(g_Kimg + (size_t)(b * NKT + kt) * KIMG_B) + kl * 20;
    uint32_t* K1 = K0 + TK * 20;
    unsigned char* V0 = g_Vimg + (size_t)(b * NKT + kt) * VIMG_B;
    uint32_t* R0 = g_Rw + ((size_t)b * NPIX + n) * 16;
    uint32_t* R1 = R0 + (size_t)BATCH * NPIX * 16;

#pragma unroll
    for (int w = 0; w < 16; ++w) {
        float va = xv[2 * w], vb = xv[2 * w + 1];
        __nv_bfloat16 a1 = __float2bfloat16(va), b1 = __float2bfloat16(vb);
        float a1f = __bfloat162float(a1), b1f = __bfloat162float(b1);
        K0[w] = pk_bf(a1f, b1f);
        K1[w] = pk_bf(va - a1f, vb - b1f);
        float ra = r[2 * w], rb = r[2 * w + 1];
        __nv_bfloat16 c1 = __float2bfloat16(ra), d1 = __float2bfloat16(rb);
        float c1f = __bfloat162float(c1), d1f = __bfloat162float(d1);
        R0[w] = pk_bf(c1f, d1f);
        R1[w] = pk_bf(ra - c1f, rb - d1f);
    }
    K0[16] = K0[17] = K0[18] = K0[19] = 0u;
    K1[16] = K1[17] = K1[18] = K1[19] = 0u;
#pragma unroll
    for (int c = 0; c < CIN; ++c)
        *(__half*)(V0 + c * VROW_B + kl * 2) = __float2half(xv[c]);
}

// ---------------------------------------------------------------------------
// HMMA flash attention. 128 threads = 4 warps x 32 query rows.
// ---------------------------------------------------------------------------
__global__ __launch_bounds__(128, 2) void attn_kernel(const float* __restrict__ xin,
                                                      float* __restrict__ out) {
    extern __shared__ unsigned char sm[];
    const int tid  = threadIdx.x, wid = tid >> 5, lane = tid & 31;
    const int tg   = lane >> 2, la = lane & 3;
    const int b    = blockIdx.x >> 5, qt = blockIdx.x & 31;
    const uint32_t smb = sm_u32(sm);

    float* sW  = (float*)(sm + SM_W);
    float* sB2 = (float*)(sm + SM_B2);
    float* sOv = (float*)(sm + SM_OV);
    for (int i = tid; i < CIN * CIN; i += 128) sW[i] = g_WovP[i];
    if (tid < CIN) sB2[tid] = g_b2[tid];

    // per-row S init: OFF - ||r_row|| * max||x||  (provable fp16-safe shift)
    const float Mb = sqrtf(__uint_as_float(g_M2[b]));
    float sh[2][2];
#pragma unroll
    for (int m = 0; m < 2; ++m)
#pragma unroll
        for (int h = 0; h < 2; ++h) {
            int row = qt * MQ + 32 * wid + 16 * m + 8 * h + tg;
            sh[m][h] = OFF - g_rn[(size_t)b * NPIX + row] * Mb;
        }

    // R fragments (resident): Ra[split][m][kblk][4]
    uint32_t Ra[2][2][2][4];
#pragma unroll
    for (int s = 0; s < 2; ++s)
#pragma unroll
        for (int m = 0; m < 2; ++m) {
            int qr = qt * MQ + 32 * wid + 16 * m + tg;
            const uint32_t* p0 = g_Rw + (((size_t)s * BATCH + b) * NPIX + qr) * 16;
            const uint32_t* p8 = p0 + 8 * 16;
#pragma unroll
            for (int k = 0; k < 2; ++k) {
                Ra[s][m][k][0] = p0[8 * k + la];
                Ra[s][m][k][1] = p8[8 * k + la];
                Ra[s][m][k][2] = p0[8 * k + la + 4];
                Ra[s][m][k][3] = p8[8 * k + la + 4];
            }
        }

    float O[2][4][4];
#pragma unroll
    for (int m = 0; m < 2; ++m)
#pragma unroll
        for (int c = 0; c < 4; ++c)
#pragma unroll
            for (int e = 0; e < 4; ++e) O[m][c][e] = 0.f;
    float l4[4] = {0.f, 0.f, 0.f, 0.f};

    // stage tile 0
    {
        const uint4* Ks = (const uint4*)(g_Kimg + (size_t)(b * NKT + 0) * KIMG_B);
        const uint4* Vs = (const uint4*)(g_Vimg + (size_t)(b * NKT + 0) * VIMG_B);
        for (int i = tid; i < KIMG_B / 16; i += 128) cp16(smb + SM_K + i * 16, Ks + i);
        for (int i = tid; i < VIMG_B / 16; i += 128) cp16(smb + SM_V + i * 16, Vs + i);
        cp_commit();
    }

#pragma unroll 1
    for (int t = 0; t < NKT; ++t) {
        if (t + 1 < NKT) {
            int nb = (t + 1) & 1;
            const uint4* Ks = (const uint4*)(g_Kimg + (size_t)(b * NKT + t + 1) * KIMG_B);
            const uint4* Vs = (const uint4*)(g_Vimg + (size_t)(b * NKT + t + 1) * VIMG_B);
            for (int i = tid; i < KIMG_B / 16; i += 128)
                cp16(smb + SM_K + nb * KIMG_B + i * 16, Ks + i);
            for (int i = tid; i < VIMG_B / 16; i += 128)
                cp16(smb + SM_V + nb * VIMG_B + i * 16, Vs + i);
            cp_commit();
            cp_wait<1>();
        } else {
            cp_wait<0>();
        }
        __syncthreads();
        const unsigned char* kb = sm + SM_K + (t & 1) * KIMG_B;
        const unsigned char* vb = sm + SM_V + (t & 1) * VIMG_B;

        // ---- QK: S = R.K^T + (OFF - bound_row)  (3 bf16 split products) ----
        float S[2][8][4];
#pragma unroll
        for (int m = 0; m < 2; ++m)
#pragma unroll
            for (int j = 0; j < 8; ++j) {
                S[m][j][0] = sh[m][0]; S[m][j][1] = sh[m][0];
                S[m][j][2] = sh[m][1]; S[m][j][3] = sh[m][1];
            }

#pragma unroll
        for (int bs = 0; bs < 2; ++bs) {
            uint32_t Bf[8][2][2];
#pragma unroll
            for (int j = 0; j < 8; ++j)
#pragma unroll
                for (int k = 0; k < 2; ++k) {
                    int off = bs * (TK * KROW_B) + ((8 * j + tg) * 20 + 8 * k + la) * 4;
                    Bf[j][k][0] = *(const uint32_t*)(kb + off);
                    Bf[j][k][1] = *(const uint32_t*)(kb + off + 16);
                }
            const int nas = bs ? 1 : 2;   // (R1,K1),(R2,K1),(R1,K2)
            for (int as = 0; as < nas; ++as)
#pragma unroll
                for (int m = 0; m < 2; ++m)
#pragma unroll
                    for (int j = 0; j < 8; ++j)
#pragma unroll
                        for (int k = 0; k < 2; ++k)
                            mma_bf16(S[m][j], Ra[as][m][k], Bf[j][k]);
        }

        // ---- softmax -> P fp16 fragments (arg <= OFF, overflow-free) ----
        uint32_t P[2][4][4];
#pragma unroll
        for (int m = 0; m < 2; ++m)
#pragma unroll
            for (int j = 0; j < 8; ++j) {
                float p0 = ex2f(S[m][j][0]), p1 = ex2f(S[m][j][1]);
                float p2 = ex2f(S[m][j][2]), p3 = ex2f(S[m][j][3]);
                l4[2 * m]     += p0 + p1;
                l4[2 * m + 1] += p2 + p3;
                int kk = j >> 1, o = (j & 1) * 2;
                P[m][kk][o]     = pk_f16(p0, p1);
                P[m][kk][o + 1] = pk_f16(p2, p3);
            }

        // ---- PV: O += P.V (single fp16 product) ----
        {
            uint32_t Vf[4][4][2];
#pragma unroll
            for (int c = 0; c < 4; ++c)
#pragma unroll
                for (int k = 0; k < 4; ++k) {
                    int off = (8 * c + tg) * VROW_B + (8 * k + la) * 4;
                    Vf[c][k][0] = *(const uint32_t*)(vb + off);
                    Vf[c][k][1] = *(const uint32_t*)(vb + off + 16);
                }
#pragma unroll
            for (int m = 0; m < 2; ++m)
#pragma unroll
                for (int c = 0; c < 4; ++c)
#pragma unroll
                    for (int k = 0; k < 4; ++k)
                        mma_f16(O[m][c], P[m][k], Vf[c][k]);
        }
        __syncthreads();
    }

    // ---- epilogue: l reduce (across la), normalize, store ov to smem ----
#pragma unroll
    for (int i = 0; i < 4; ++i) {
        l4[i] += __shfl_xor_sync(0xFFFFFFFFu, l4[i], 1);
        l4[i] += __shfl_xor_sync(0xFFFFFFFFu, l4[i], 2);
        asm("rcp.approx.f32 %0, %1;" : "+f"(l4[i]) : "f"(l4[i]));
    }
#pragma unroll
    for (int m = 0; m < 2; ++m)
#pragma unroll
        for (int h = 0; h < 2; ++h) {
            int row = 32 * wid + 16 * m + 8 * h + tg;
            float inv = l4[2 * m + h];
#pragma unroll
            for (int c = 0; c < 4; ++c) {
                sOv[row * 33 + 8 * c + 2 * la]     = O[m][c][2 * h]     * inv;
                sOv[row * 33 + 8 * c + 2 * la + 1] = O[m][c][2 * h + 1] * inv;
            }
        }
    __syncthreads();

    // ---- fused projection + bias + residual (1 query/thread) ----
    float ov[CIN], y[CIN];
#pragma unroll
    for (int c = 0; c < CIN; ++c) ov[c] = sOv[tid * 33 + c];
#pragma unroll
    for (int c = 0; c < CIN; ++c) y[c] = sB2[c];
#pragma unroll 4
    for (int j = 0; j < CIN; ++j) {
        float pj = ov[j];
        const float* wp = sW + j * CIN;
#pragma unroll
        for (int c = 0; c < CIN; ++c) y[c] += pj * wp[c];
    }
    int n = qt * MQ + tid;
    const float* xp = xin + (size_t)b * CIN * NPIX + n;
    float*       op = out + (size_t)b * CIN * NPIX + n;
#pragma unroll
    for (int c = 0; c < CIN; ++c)
        op[(size_t)c * NPIX] = y[c] + xp[(size_t)c * NPIX];
}

// ---------------------------------------------------------------------------
extern "C" void kernel_launch(void* const* d_in, const int* in_sizes, int n_in,
                              void* d_out, int out_size) {
    (void)in_sizes; (void)n_in; (void)out_size;
    const float* x  = (const float*)d_in[0];
    const float* wq = (const float*)d_in[1];
    const float* bq = (const float*)d_in[2];
    const float* wk = (const float*)d_in[3];
    // d_in[4] = bk: cancels in softmax, unused
    const float* wv = (const float*)d_in[5];
    const float* bv = (const float*)d_in[6];
    const float* wo = (const float*)d_in[7];
    const float* bo = (const float*)d_in[8];
    float* out = (float*)d_out;

    cudaFuncSetAttribute(attn_kernel, cudaFuncAttributeMaxDynamicSharedMemorySize, SM_TOTAL);

    derive_kernel<<<2, 1024>>>(wq, bq, wk, wv, wo, bv, bo);
    tq_kernel<<<dim3(NPIX / 256, BATCH), 256>>>(x);
    attn_kernel<<<BATCH * (NPIX / MQ), 128, SM_TOTAL>>>(x, out);
}